// round 1
// baseline (speedup 1.0000x reference)
#include <cuda_runtime.h>

#define B  4
#define LQ 512
#define LK 512
#define E  128
#define D  256
#define TL 8          // l-rows per CTA in the main kernel

// Scratch for projected q/k (allocation-free rule: __device__ globals)
__device__ float g_qproj[B * LQ * E];
__device__ float g_kproj[B * LK * E];

__device__ __forceinline__ float tanha(float x) {
    float t;
    asm("tanh.approx.f32 %0, %1;" : "=f"(t) : "f"(x));
    return t;
}

// ---------------------------------------------------------------------------
// Projection: out[r][e] = sum_d X[r][d] * W[d][e], rows = B*L (2048), D=256, E=128
// blockIdx.y: 0 -> (query, Wc1, g_qproj), 1 -> (key, Wc2, g_kproj)
// 128 threads (one per e), 4 rows per block.
// ---------------------------------------------------------------------------
__global__ __launch_bounds__(128) void proj_kernel(
    const float* __restrict__ query, const float* __restrict__ key,
    const float* __restrict__ Wc1,   const float* __restrict__ Wc2)
{
    const float* X; const float* W; float* O;
    if (blockIdx.y == 0) { X = query; W = Wc1; O = g_qproj; }
    else                 { X = key;   W = Wc2; O = g_kproj; }

    const int row0 = blockIdx.x * 4;
    const int tid  = threadIdx.x;   // 0..127 == e

    __shared__ float xs[4 * D];
    const float4* xv = (const float4*)(X + (size_t)row0 * D);
    #pragma unroll
    for (int i = tid; i < 4 * D / 4; i += 128)
        ((float4*)xs)[i] = xv[i];
    __syncthreads();

    float a0 = 0.f, a1 = 0.f, a2 = 0.f, a3 = 0.f;
    #pragma unroll 8
    for (int d = 0; d < D; d++) {
        float w = W[d * E + tid];           // coalesced, L1-resident (128KB)
        a0 += xs[d        ] * w;
        a1 += xs[D   + d  ] * w;
        a2 += xs[2*D + d  ] * w;
        a3 += xs[3*D + d  ] * w;
    }
    O[(size_t)(row0 + 0) * E + tid] = a0;
    O[(size_t)(row0 + 1) * E + tid] = a1;
    O[(size_t)(row0 + 2) * E + tid] = a2;
    O[(size_t)(row0 + 3) * E + tid] = a3;
}

// ---------------------------------------------------------------------------
// Fused scores + softmax + context.
// Grid: (LK/TL, B). 256 threads = 8 warps.
// Phase 1: warp w owns l = l0 + w. qproj staged in 32-qq tiles (padded rows,
//          conflict-free float4 LDS). lane = qq within tile; full e-reduction
//          accumulates in a register (no shuffles in the MUFU hot loop).
// Phase 2: per-warp softmax over 512 scores (16 vals/lane + shfl reduce).
// Phase 3: context GEMV, float4 over D, 2 l-rows per thread.
// ---------------------------------------------------------------------------
__global__ __launch_bounds__(256) void atten_kernel(
    const float* __restrict__ value, const float* __restrict__ vc,
    float* __restrict__ ctx_out, float* __restrict__ att_out)
{
    const int b    = blockIdx.y;
    const int l0   = blockIdx.x * TL;
    const int tid  = threadIdx.x;
    const int w    = tid >> 5;
    const int lane = tid & 31;

    __shared__ float ks[TL][E];        // 4 KB
    __shared__ float vcs[E];           // 0.5 KB
    __shared__ float qs[32][132];      // 16.9 KB, +4 pad: conflict-free & 16B-aligned rows
    __shared__ float ps[TL][LQ];       // 16 KB: scores, then probabilities

    // load k rows + vc
    for (int i = tid; i < TL * E; i += 256)
        ks[i >> 7][i & 127] = g_kproj[(size_t)(b * LK + l0 + (i >> 7)) * E + (i & 127)];
    if (tid < E) vcs[tid] = vc[tid];

    // ---- Phase 1: scores ----
    const float4* qbase = (const float4*)(g_qproj + (size_t)b * LQ * E);
    #pragma unroll 1
    for (int tile = 0; tile < LQ / 32; tile++) {
        __syncthreads();                                  // covers ks/vcs on iter 0, qs reuse after
        const float4* src = qbase + tile * 32 * (E / 4);
        #pragma unroll
        for (int i = tid; i < 32 * E / 4; i += 256)       // 16KB contiguous -> padded smem
            *(float4*)&qs[i >> 5][(i & 31) * 4] = src[i];
        __syncthreads();

        const float4* qp = (const float4*)qs[lane];
        const float4* kp = (const float4*)ks[w];
        const float4* vp = (const float4*)vcs;
        float a = 0.f;
        #pragma unroll 8
        for (int e4 = 0; e4 < E / 4; e4++) {
            float4 q = qp[e4];
            float4 k = kp[e4];
            float4 v = vp[e4];
            a += v.x * tanha(q.x + k.x);
            a += v.y * tanha(q.y + k.y);
            a += v.z * tanha(q.z + k.z);
            a += v.w * tanha(q.w + k.w);
        }
        ps[w][tile * 32 + lane] = a;
    }
    __syncwarp();

    // ---- Phase 2: softmax over qq (per warp, l = l0 + w) ----
    float vals[LQ / 32];
    float m = -1e30f;
    #pragma unroll
    for (int k = 0; k < LQ / 32; k++) {
        vals[k] = ps[w][lane + 32 * k];
        m = fmaxf(m, vals[k]);
    }
    #pragma unroll
    for (int o = 16; o; o >>= 1) m = fmaxf(m, __shfl_xor_sync(0xffffffffu, m, o));
    float s = 0.f;
    #pragma unroll
    for (int k = 0; k < LQ / 32; k++) {
        vals[k] = __expf(vals[k] - m);
        s += vals[k];
    }
    #pragma unroll
    for (int o = 16; o; o >>= 1) s += __shfl_xor_sync(0xffffffffu, s, o);
    const float inv = __fdividef(1.f, s);

    float* arow = att_out + (size_t)(b * LK + l0 + w) * LQ;
    #pragma unroll
    for (int k = 0; k < LQ / 32; k++) {
        float p = vals[k] * inv;
        ps[w][lane + 32 * k] = p;       // reused by phase 3
        arow[lane + 32 * k]  = p;       // coalesced 128B stores
    }
    __syncthreads();

    // ---- Phase 3: context = atten @ value ----
    const int d4 = tid & 63;            // float4 column
    const int lg = tid >> 6;            // 0..3; handles l-rows lg and lg+4
    const float4* vbase = (const float4*)(value + (size_t)b * LQ * D);
    float4 c0 = make_float4(0.f, 0.f, 0.f, 0.f);
    float4 c1 = make_float4(0.f, 0.f, 0.f, 0.f);
    #pragma unroll 4
    for (int qq = 0; qq < LQ; qq++) {
        float4 v  = vbase[qq * (D / 4) + d4];   // coalesced 1KB/warp-group, L2/L1 resident
        float p0  = ps[lg][qq];                 // smem broadcast within warp
        float p1  = ps[lg + 4][qq];
        c0.x += p0 * v.x; c0.y += p0 * v.y; c0.z += p0 * v.z; c0.w += p0 * v.w;
        c1.x += p1 * v.x; c1.y += p1 * v.y; c1.z += p1 * v.z; c1.w += p1 * v.w;
    }
    float4* cout = (float4*)ctx_out;
    cout[(size_t)(b * LK + l0 + lg    ) * (D / 4) + d4] = c0;
    cout[(size_t)(b * LK + l0 + lg + 4) * (D / 4) + d4] = c1;
}

// ---------------------------------------------------------------------------
extern "C" void kernel_launch(void* const* d_in, const int* in_sizes, int n_in,
                              void* d_out, int out_size)
{
    const float* query = (const float*)d_in[0];
    const float* key   = (const float*)d_in[1];
    const float* value = (const float*)d_in[2];
    const float* Wc1   = (const float*)d_in[3];
    const float* Wc2   = (const float*)d_in[4];
    const float* vc    = (const float*)d_in[5];

    float* ctx = (float*)d_out;                 // [B, LK, D]
    float* att = ctx + (size_t)B * LK * D;      // [B, LK, LQ]

    proj_kernel<<<dim3(B * LQ / 4, 2), 128>>>(query, key, Wc1, Wc2);
    atten_kernel<<<dim3(LK / TL, B), 256>>>(value, vc, ctx, att);
}